// round 16
// baseline (speedup 1.0000x reference)
#include <cuda_runtime.h>
#include <cuda_fp16.h>
#include <cstdint>

#define B_ 8
#define T_ 4096
#define C_ 1024
#define H_ 128
#define M_ (B_ * T_)   // 32768

// ---------------- device scratch (allocation-free rule) ----------------
__device__ __half g_x16[(size_t)M_ * C_];
__device__ __half g_w16[3][(size_t)H_ * C_];
__device__ __half g_q16[(size_t)M_ * H_];
__device__ __half g_k16[(size_t)M_ * H_];
__device__ __half g_v16[(size_t)M_ * H_];

// ---------------- helpers ----------------
__device__ __forceinline__ uint32_t smem_u32(const void* p) {
    uint32_t a;
    asm("{ .reg .u64 t; cvta.to.shared.u64 t, %1; cvt.u32.u64 %0, t; }"
        : "=r"(a) : "l"(p));
    return a;
}
__device__ __forceinline__ void ldsm4(uint32_t r[4], uint32_t a) {
    asm volatile("ldmatrix.sync.aligned.m8n8.x4.shared.b16 {%0,%1,%2,%3}, [%4];"
        : "=r"(r[0]), "=r"(r[1]), "=r"(r[2]), "=r"(r[3]) : "r"(a));
}
__device__ __forceinline__ void ldsm4t(uint32_t r[4], uint32_t a) {
    asm volatile("ldmatrix.sync.aligned.m8n8.x4.trans.shared.b16 {%0,%1,%2,%3}, [%4];"
        : "=r"(r[0]), "=r"(r[1]), "=r"(r[2]), "=r"(r[3]) : "r"(a));
}
__device__ __forceinline__ void mma16816(float c[4], const uint32_t a[4],
                                         uint32_t b0, uint32_t b1) {
    asm volatile(
        "mma.sync.aligned.m16n8k16.row.col.f32.f16.f16.f32 "
        "{%0,%1,%2,%3}, {%4,%5,%6,%7}, {%8,%9}, {%0,%1,%2,%3};"
        : "+f"(c[0]), "+f"(c[1]), "+f"(c[2]), "+f"(c[3])
        : "r"(a[0]), "r"(a[1]), "r"(a[2]), "r"(a[3]), "r"(b0), "r"(b1));
}
__device__ __forceinline__ uint32_t pack_h2(float a, float b) {
    __half2 h = __floats2half2_rn(a, b);
    return *reinterpret_cast<uint32_t*>(&h);
}
// exp2 of two fp32 values -> packed fp16x2 (single 2-wide MUFU)
__device__ __forceinline__ uint32_t exp2_h2(float a, float b) {
    uint32_t p = pack_h2(a, b);
    uint32_t r;
    asm("ex2.approx.f16x2 %0, %1;" : "=r"(r) : "r"(p));
    return r;
}

#define CP16(dst, src) \
    asm volatile("cp.async.cg.shared.global [%0], [%1], 16;" \
                 :: "r"(dst), "l"(src) : "memory")
#define CP_COMMIT() asm volatile("cp.async.commit_group;" ::: "memory")
#define CP_WAIT0()  asm volatile("cp.async.wait_group 0;" ::: "memory")
#define CP_WAIT2()  asm volatile("cp.async.wait_group 2;" ::: "memory")

// ---------------- fp32 -> fp16 conversions ----------------
__global__ __launch_bounds__(256) void convert_x_kernel(const float* __restrict__ x)
{
    size_t i = (size_t)blockIdx.x * 256 + threadIdx.x;
    float4 v = ((const float4*)x)[i];
    uint2 o;
    o.x = pack_h2(v.x, v.y);
    o.y = pack_h2(v.z, v.w);
    ((uint2*)g_x16)[i] = o;
}
__global__ __launch_bounds__(256) void convert_w_kernel(
    const float* __restrict__ Wk, const float* __restrict__ Wq,
    const float* __restrict__ Wv)
{
    const int sel = blockIdx.y;
    const float* W = (sel == 0) ? Wq : (sel == 1) ? Wk : Wv;
    size_t i = (size_t)blockIdx.x * 256 + threadIdx.x;
    float4 v = ((const float4*)W)[i];
    uint2 o;
    o.x = pack_h2(v.x, v.y);
    o.y = pack_h2(v.z, v.w);
    ((uint2*)g_w16[sel])[i] = o;
}

// ---------------- QKV projection: M=64 CTAs, 128 thr, 4 CTAs/SM -------------
// Warps 2Mx2N: each warp 32(M) x 64(N). 2-stage ring; barrier doubles as the
// write-safety fence (WAIT0 -> sync -> issue(next) -> compute).
#define PSTR   72
#define PAARR  (64 * PSTR)             // A elems per stage
#define PBARR  (128 * PSTR)            // B elems per stage
#define PSTAGE (PAARR + PBARR)         // 13824 halfs = 27648 B
#define P_SMEM (2 * PSTAGE * 2)        // 55296 B -> 4 CTAs/SM

__global__ __launch_bounds__(128, 4) void qkv_mma_kernel()
{
    extern __shared__ __half ps[];

    const int tid = threadIdx.x, lane = tid & 31, w = tid >> 5;   // w: 0..3
    const int wm = w & 1;              // M half (32 rows)
    const int wn = w >> 1;             // N half (64 cols)
    const int sel = blockIdx.x;
    const int m0  = blockIdx.y * 64;

    const __half* xp = g_x16 + (size_t)m0 * C_;
    const __half* wp = g_w16[sel];

    const uint32_t base = smem_u32(ps);

    // cp.async offsets: A = 512 uint4 (4/thread), B = 1024 uint4 (8/thread)
    uint32_t cpa[4], cpb[8];
    int      gas[4], gbs[8];
#pragma unroll
    for (int it = 0; it < 4; it++) {
        int i   = tid + it * 128;          // 0..511
        int row = i >> 3, c8 = (i & 7) * 8;
        cpa[it] = (uint32_t)(row * PSTR + c8) * 2;
        gas[it] = row * C_ + c8;
    }
#pragma unroll
    for (int it = 0; it < 8; it++) {
        int i   = tid + it * 128;          // 0..1023
        int row = i >> 3, c8 = (i & 7) * 8;
        cpb[it] = (uint32_t)(row * PSTR + c8) * 2;
        gbs[it] = row * C_ + c8;
    }

    auto issue = [&](int kc, int s) {
        const int k0 = kc * 64;
        const uint32_t sa = base + (uint32_t)(s * PSTAGE) * 2;
        const uint32_t sb = sa + (uint32_t)PAARR * 2;
#pragma unroll
        for (int it = 0; it < 4; it++)
            CP16(sa + cpa[it], (const char*)(xp + (size_t)gas[it] + k0));
#pragma unroll
        for (int it = 0; it < 8; it++)
            CP16(sb + cpb[it], (const char*)(wp + (size_t)gbs[it] + k0));
    };

    float of[16][4];
#pragma unroll
    for (int j = 0; j < 16; j++)
#pragma unroll
        for (int e = 0; e < 4; e++) of[j][e] = 0.f;

    const uint32_t a_off = (uint32_t)(wm * 32 + (lane & 15)) * (PSTR * 2)
                         + (lane >> 4) * 16;
    const uint32_t b_off = (uint32_t)(wn * 64 + (lane & 7) + ((lane >> 4) & 1) * 8)
                         * (PSTR * 2) + ((lane >> 3) & 1) * 16;

    issue(0, 0);
    CP_COMMIT();

    const int NC = C_ / 64;   // 16
    for (int kc = 0; kc < NC; kc++) {
        CP_WAIT0();           // chunk kc resident (issued last iteration)
        __syncthreads();      // all warps past compute(kc-1); safe to overwrite
        if (kc + 1 < NC) {
            issue(kc + 1, (kc + 1) & 1);
            CP_COMMIT();      // flies during compute(kc)
        }

        const uint32_t sa   = base + (uint32_t)((kc & 1) * PSTAGE) * 2;
        const uint32_t sx_b = sa;
        const uint32_t sw_b = sa + (uint32_t)PAARR * 2;

#pragma unroll
        for (int u = 0; u < 4; u++) {
            uint32_t a0[4], a1[4];
            ldsm4(a0, sx_b + a_off + u * 32);
            ldsm4(a1, sx_b + a_off + (uint32_t)16 * (PSTR * 2) + u * 32);
#pragma unroll
            for (int jp = 0; jp < 4; jp++) {
                uint32_t bh[4];
                ldsm4(bh, sw_b + b_off + (uint32_t)jp * 16 * (PSTR * 2) + u * 32);
                mma16816(of[2 * jp],         a0, bh[0], bh[1]);
                mma16816(of[2 * jp + 1],     a0, bh[2], bh[3]);
                mma16816(of[8 + 2 * jp],     a1, bh[0], bh[1]);
                mma16816(of[8 + 2 * jp + 1], a1, bh[2], bh[3]);
            }
        }
    }

    // q scale folds softmax 1/sqrt(H) AND log2(e) (flash works in exp2 domain)
    const float scl = (sel == 0) ? (1.4426950408889634f * 0.08838834764831845f)
                                 : 1.0f;
    __half* op = (sel == 0) ? g_q16 : (sel == 1) ? g_k16 : g_v16;
#pragma unroll
    for (int j = 0; j < 16; j++) {
        const int mf = j >> 3;                 // 16-row half within warp M tile
        const int jp = (j >> 1) & 3;           // 16-col group within warp N tile
        const int h  = j & 1;                  // n8 half
#pragma unroll
        for (int i = 0; i < 2; i++) {
            const size_t row = (size_t)(m0 + wm * 32 + mf * 16 + (lane >> 2) + 8 * i);
            const int col = wn * 64 + jp * 16 + h * 8 + (lane & 3) * 2;
            *(uint32_t*)&op[row * H_ + col] =
                pack_h2(of[j][2 * i] * scl, of[j][2 * i + 1] * scl);
        }
    }
}

// ---------------- flash attention: fp16 mma, 4-stage KV ring, exp2 softmax ----
// (R8 configuration: BM=128, 256 threads, no tail sync — best measured)
#define FSTR   136
#define FQ     (128 * FSTR)
#define FKV    (64 * FSTR)
#define FSTAGE (2 * FKV)                      // K + V
#define F_SMEM ((FQ + 4 * FSTAGE) * 2)        // 174080 B

__global__ __launch_bounds__(256) void flash_kernel(float* __restrict__ out)
{
    extern __shared__ __half fs[];
    __half* sq = fs;

    const int tid = threadIdx.x, lane = tid & 31, w = tid >> 5;
    const int b   = blockIdx.x;
    const int r0  = (gridDim.y - 1 - blockIdx.y) * 128;   // heavy rows first
    const int wr0 = w * 16;

    const uint32_t base   = smem_u32(fs);
    const uint32_t kvbase = base + (uint32_t)FQ * 2;

    uint32_t cpo[4];
    int      go[4];
#pragma unroll
    for (int it = 0; it < 4; it++) {
        int i   = tid + it * 256;            // 1024 uint4 per array
        int row = i >> 4, c8 = (i & 15) * 8;
        cpo[it] = (uint32_t)(row * FSTR + c8) * 2;
        go[it]  = row * H_ + c8;
    }

    const size_t bbase = (size_t)b * T_ * H_;
    auto issue = [&](int t, int s) {
        const size_t off = bbase + (size_t)t * 64 * H_;
        const __half* kp = g_k16 + off;
        const __half* vp = g_v16 + off;
        const uint32_t sb = kvbase + (uint32_t)(s * FSTAGE) * 2;
#pragma unroll
        for (int it = 0; it < 4; it++) {
            CP16(sb + cpo[it],             (const char*)(kp + go[it]));
            CP16(sb + FKV * 2 + cpo[it],   (const char*)(vp + go[it]));
        }
    };

    const int ntiles = r0 / 64 + 2;

    // prologue: 2 tiles in flight, then load Q
    issue(0, 0); CP_COMMIT();
    issue(1, 1); CP_COMMIT();

    const uint4* qp = (const uint4*)(g_q16 + bbase + (size_t)r0 * H_);
#pragma unroll
    for (int it = 0; it < 8; it++) {
        int i = tid + it * 256;               // 2048 uint4
        int row = i >> 4, c8 = (i & 15) * 8;
        *(uint4*)&sq[row * FSTR + c8] = qp[i];
    }
    __syncthreads();

    const uint32_t qa_off = (uint32_t)(wr0 + (lane & 15)) * (FSTR * 2) + (lane >> 4) * 16;
    const uint32_t kb_off = (uint32_t)((lane & 7) + ((lane >> 4) & 1) * 8) * (FSTR * 2)
                          + ((lane >> 3) & 1) * 16;
    const uint32_t vb_off = (uint32_t)((lane & 7) + ((lane >> 3) & 1) * 8) * (FSTR * 2)
                          + ((lane >> 4) & 1) * 16;

    uint32_t qf[8][4];
#pragma unroll
    for (int u = 0; u < 8; u++) ldsm4(qf[u], base + qa_off + u * 32);

    float of[16][4];
#pragma unroll
    for (int j = 0; j < 16; j++)
#pragma unroll
        for (int e = 0; e < 4; e++) of[j][e] = 0.f;
    float m_i[2] = {-1e30f, -1e30f}, l_i[2] = {0.f, 0.f};

    for (int t = 0; t < ntiles; t++) {
        const int s0 = t * 64;
        if (t + 2 < ntiles) issue(t + 2, (t + 2) & 3);
        CP_COMMIT();          // unconditional: empty groups keep WAIT2 counting safe
        CP_WAIT2();
        __syncthreads();

        const uint32_t sb   = kvbase + (uint32_t)((t & 3) * FSTAGE) * 2;
        const uint32_t sk_b = sb;
        const uint32_t sv_b = sb + FKV * 2;

        // ---- S = Q K^T  (logits already in log2 domain via q scale) ----
        float sf[8][4];
#pragma unroll
        for (int j = 0; j < 8; j++)
#pragma unroll
            for (int e = 0; e < 4; e++) sf[j][e] = 0.f;

#pragma unroll
        for (int u = 0; u < 8; u++) {
#pragma unroll
            for (int jp = 0; jp < 4; jp++) {
                uint32_t bh[4];
                ldsm4(bh, sk_b + kb_off + (uint32_t)jp * 16 * (FSTR * 2) + u * 32);
                mma16816(sf[2 * jp],     qf[u], bh[0], bh[1]);
                mma16816(sf[2 * jp + 1], qf[u], bh[2], bh[3]);
            }
        }

        // ---- causal mask ----
        const int rowg0 = r0 + wr0 + (lane >> 2);
        if (s0 + 63 > rowg0) {
#pragma unroll
            for (int j = 0; j < 8; j++) {
                const int colg = s0 + 8 * j + (lane & 3) * 2;
#pragma unroll
                for (int i = 0; i < 2; i++) {
                    const int rg = rowg0 + 8 * i;
                    if (colg     > rg) sf[j][2 * i]     = -1e30f;
                    if (colg + 1 > rg) sf[j][2 * i + 1] = -1e30f;
                }
            }
        }

        // ---- online softmax (exp2 domain, 2-wide f16 EX2 -> packed P) ----
        uint32_t pf[8][2];
#pragma unroll
        for (int i = 0; i < 2; i++) {
            float mx = sf[0][2 * i];
#pragma unroll
            for (int j = 0; j < 8; j++) {
                mx = fmaxf(mx, sf[j][2 * i]);
                mx = fmaxf(mx, sf[j][2 * i + 1]);
            }
            mx = fmaxf(mx, __shfl_xor_sync(0xffffffffu, mx, 1));
            mx = fmaxf(mx, __shfl_xor_sync(0xffffffffu, mx, 2));
            const float mn  = fmaxf(m_i[i], mx);
            const float fac = exp2f(m_i[i] - mn);
            m_i[i] = mn;
            float rs = 0.f;
#pragma unroll
            for (int j = 0; j < 8; j++) {
                const uint32_t p2 = exp2_h2(sf[j][2 * i] - mn, sf[j][2 * i + 1] - mn);
                pf[j][i] = p2;
                const float2 pv = __half22float2(*reinterpret_cast<const __half2*>(&p2));
                rs += pv.x + pv.y;
            }
            rs += __shfl_xor_sync(0xffffffffu, rs, 1);
            rs += __shfl_xor_sync(0xffffffffu, rs, 2);
            l_i[i] = l_i[i] * fac + rs;
#pragma unroll
            for (int j = 0; j < 16; j++) {
                of[j][2 * i] *= fac; of[j][2 * i + 1] *= fac;
            }
        }

        // ---- O += P V ----
#pragma unroll
        for (int u = 0; u < 4; u++) {
            uint32_t ph[4];
            ph[0] = pf[2 * u][0];
            ph[1] = pf[2 * u][1];
            ph[2] = pf[2 * u + 1][0];
            ph[3] = pf[2 * u + 1][1];
#pragma unroll
            for (int jp = 0; jp < 8; jp++) {
                uint32_t vh[4];
                ldsm4t(vh, sv_b + vb_off + (uint32_t)u * 16 * (FSTR * 2) + jp * 32);
                mma16816(of[2 * jp],     ph, vh[0], vh[1]);
                mma16816(of[2 * jp + 1], ph, vh[2], vh[3]);
            }
        }
        // no tail sync: 4-stage ring makes the write stage disjoint from any
        // stage readable by a warp at most one iteration behind the top sync.
    }

    // ---- write O ----
    const float inv0 = 1.0f / l_i[0], inv1 = 1.0f / l_i[1];
#pragma unroll
    for (int j = 0; j < 16; j++)
#pragma unroll
        for (int i = 0; i < 2; i++) {
            const size_t row = (size_t)b * T_ + r0 + wr0 + (lane >> 2) + 8 * i;
            const int col = 8 * j + (lane & 3) * 2;
            const float inv = i ? inv1 : inv0;
            float2 v = make_float2(of[j][2 * i] * inv, of[j][2 * i + 1] * inv);
            *(float2*)&out[row * H_ + col] = v;
        }
}

// ---------------------------------------------------------------------------
extern "C" void kernel_launch(void* const* d_in, const int* in_sizes, int n_in,
                              void* d_out, int out_size)
{
    const float* x  = (const float*)d_in[0];
    const float* Wk = (const float*)d_in[1];
    const float* Wq = (const float*)d_in[2];
    const float* Wv = (const float*)d_in[3];
    float* out = (float*)d_out;

    cudaFuncSetAttribute(qkv_mma_kernel,
                         cudaFuncAttributeMaxDynamicSharedMemorySize, P_SMEM);
    cudaFuncSetAttribute(flash_kernel,
                         cudaFuncAttributeMaxDynamicSharedMemorySize, F_SMEM);

    convert_x_kernel<<<(M_ * (size_t)C_ / 4) / 256, 256>>>(x);
    convert_w_kernel<<<dim3((H_ * C_ / 4) / 256, 3, 1), 256>>>(Wk, Wq, Wv);
    qkv_mma_kernel<<<dim3(3, M_ / 64, 1), 128, P_SMEM>>>();
    flash_kernel<<<dim3(B_, T_ / 128, 1), 256, F_SMEM>>>(out);
}

// round 17
// speedup vs baseline: 1.0247x; 1.0247x over previous
#include <cuda_runtime.h>
#include <cuda_fp16.h>
#include <cstdint>

#define B_ 8
#define T_ 4096
#define C_ 1024
#define H_ 128
#define M_ (B_ * T_)   // 32768

// ---------------- device scratch (allocation-free rule) ----------------
__device__ __half g_x16[(size_t)M_ * C_];
__device__ __half g_w16[3][(size_t)H_ * C_];
__device__ __half g_q16[(size_t)M_ * H_];
__device__ __half g_k16[(size_t)M_ * H_];
__device__ __half g_v16[(size_t)M_ * H_];

// ---------------- helpers ----------------
__device__ __forceinline__ uint32_t smem_u32(const void* p) {
    uint32_t a;
    asm("{ .reg .u64 t; cvta.to.shared.u64 t, %1; cvt.u32.u64 %0, t; }"
        : "=r"(a) : "l"(p));
    return a;
}
__device__ __forceinline__ void ldsm4(uint32_t r[4], uint32_t a) {
    asm volatile("ldmatrix.sync.aligned.m8n8.x4.shared.b16 {%0,%1,%2,%3}, [%4];"
        : "=r"(r[0]), "=r"(r[1]), "=r"(r[2]), "=r"(r[3]) : "r"(a));
}
__device__ __forceinline__ void ldsm4t(uint32_t r[4], uint32_t a) {
    asm volatile("ldmatrix.sync.aligned.m8n8.x4.trans.shared.b16 {%0,%1,%2,%3}, [%4];"
        : "=r"(r[0]), "=r"(r[1]), "=r"(r[2]), "=r"(r[3]) : "r"(a));
}
__device__ __forceinline__ void mma16816(float c[4], const uint32_t a[4],
                                         uint32_t b0, uint32_t b1) {
    asm volatile(
        "mma.sync.aligned.m16n8k16.row.col.f32.f16.f16.f32 "
        "{%0,%1,%2,%3}, {%4,%5,%6,%7}, {%8,%9}, {%0,%1,%2,%3};"
        : "+f"(c[0]), "+f"(c[1]), "+f"(c[2]), "+f"(c[3])
        : "r"(a[0]), "r"(a[1]), "r"(a[2]), "r"(a[3]), "r"(b0), "r"(b1));
}
__device__ __forceinline__ uint32_t pack_h2(float a, float b) {
    __half2 h = __floats2half2_rn(a, b);
    return *reinterpret_cast<uint32_t*>(&h);
}
// exp2 of two fp32 values -> packed fp16x2 (single 2-wide MUFU)
__device__ __forceinline__ uint32_t exp2_h2(float a, float b) {
    uint32_t p = pack_h2(a, b);
    uint32_t r;
    asm("ex2.approx.f16x2 %0, %1;" : "=r"(r) : "r"(p));
    return r;
}

#define CP16(dst, src) \
    asm volatile("cp.async.cg.shared.global [%0], [%1], 16;" \
                 :: "r"(dst), "l"(src) : "memory")
#define CP_COMMIT() asm volatile("cp.async.commit_group;" ::: "memory")
#define CP_WAIT0()  asm volatile("cp.async.wait_group 0;" ::: "memory")

// mbarrier ops (cta scope)
#define MBAR_INIT(addr, cnt) \
    asm volatile("mbarrier.init.shared.b64 [%0], %1;" :: "r"(addr), "r"(cnt) : "memory")
#define MBAR_ARRIVE(addr) \
    asm volatile("mbarrier.arrive.shared.b64 _, [%0];" :: "r"(addr) : "memory")
#define CP_MBAR_ARRIVE(addr) \
    asm volatile("cp.async.mbarrier.arrive.noinc.shared::cta.b64 [%0];" \
                 :: "r"(addr) : "memory")
#define MBAR_WAIT(addr, parity) do {                                          \
    uint32_t _m = (addr); uint32_t _p = (parity); uint32_t _d;                \
    asm volatile("{\n\t.reg .pred p;\n\t"                                     \
        "mbarrier.try_wait.parity.acquire.cta.shared::cta.b64 p, [%1], %2;\n\t" \
        "selp.b32 %0, 1, 0, p;\n\t}" : "=r"(_d) : "r"(_m), "r"(_p) : "memory"); \
    if (!_d) {                                                                \
        asm volatile("{\n\t.reg .pred P1;\n\t"                                \
            "WL%=:\n\t"                                                       \
            "mbarrier.try_wait.parity.acquire.cta.shared::cta.b64 P1, [%0], %1, 0x989680;\n\t" \
            "@P1 bra.uni WD%=;\n\t"                                           \
            "bra.uni WL%=;\n\t"                                               \
            "WD%=:\n\t}" :: "r"(_m), "r"(_p) : "memory");                     \
    } } while (0)

// ---------------- fp32 -> fp16 conversions ----------------
__global__ __launch_bounds__(256) void convert_x_kernel(const float* __restrict__ x)
{
    size_t i = (size_t)blockIdx.x * 256 + threadIdx.x;
    float4 v = ((const float4*)x)[i];
    uint2 o;
    o.x = pack_h2(v.x, v.y);
    o.y = pack_h2(v.z, v.w);
    ((uint2*)g_x16)[i] = o;
}
__global__ __launch_bounds__(256) void convert_w_kernel(
    const float* __restrict__ Wk, const float* __restrict__ Wq,
    const float* __restrict__ Wv)
{
    const int sel = blockIdx.y;
    const float* W = (sel == 0) ? Wq : (sel == 1) ? Wk : Wv;
    size_t i = (size_t)blockIdx.x * 256 + threadIdx.x;
    float4 v = ((const float4*)W)[i];
    uint2 o;
    o.x = pack_h2(v.x, v.y);
    o.y = pack_h2(v.z, v.w);
    ((uint2*)g_w16[sel])[i] = o;
}

// ---------------- QKV projection: M=64 CTAs, 128 thr, 4 CTAs/SM -------------
// (measured-neutral-vs-best config; keep as benched)
#define PSTR   72
#define PAARR  (64 * PSTR)             // A elems per stage
#define PBARR  (128 * PSTR)            // B elems per stage
#define PSTAGE (PAARR + PBARR)         // 13824 halfs = 27648 B
#define P_SMEM (2 * PSTAGE * 2)        // 55296 B -> 4 CTAs/SM

__global__ __launch_bounds__(128, 4) void qkv_mma_kernel()
{
    extern __shared__ __half ps[];

    const int tid = threadIdx.x, lane = tid & 31, w = tid >> 5;   // w: 0..3
    const int wm = w & 1;              // M half (32 rows)
    const int wn = w >> 1;             // N half (64 cols)
    const int sel = blockIdx.x;
    const int m0  = blockIdx.y * 64;

    const __half* xp = g_x16 + (size_t)m0 * C_;
    const __half* wp = g_w16[sel];

    const uint32_t base = smem_u32(ps);

    uint32_t cpa[4], cpb[8];
    int      gas[4], gbs[8];
#pragma unroll
    for (int it = 0; it < 4; it++) {
        int i   = tid + it * 128;          // 0..511
        int row = i >> 3, c8 = (i & 7) * 8;
        cpa[it] = (uint32_t)(row * PSTR + c8) * 2;
        gas[it] = row * C_ + c8;
    }
#pragma unroll
    for (int it = 0; it < 8; it++) {
        int i   = tid + it * 128;          // 0..1023
        int row = i >> 3, c8 = (i & 7) * 8;
        cpb[it] = (uint32_t)(row * PSTR + c8) * 2;
        gbs[it] = row * C_ + c8;
    }

    auto issue = [&](int kc, int s) {
        const int k0 = kc * 64;
        const uint32_t sa = base + (uint32_t)(s * PSTAGE) * 2;
        const uint32_t sb = sa + (uint32_t)PAARR * 2;
#pragma unroll
        for (int it = 0; it < 4; it++)
            CP16(sa + cpa[it], (const char*)(xp + (size_t)gas[it] + k0));
#pragma unroll
        for (int it = 0; it < 8; it++)
            CP16(sb + cpb[it], (const char*)(wp + (size_t)gbs[it] + k0));
    };

    float of[16][4];
#pragma unroll
    for (int j = 0; j < 16; j++)
#pragma unroll
        for (int e = 0; e < 4; e++) of[j][e] = 0.f;

    const uint32_t a_off = (uint32_t)(wm * 32 + (lane & 15)) * (PSTR * 2)
                         + (lane >> 4) * 16;
    const uint32_t b_off = (uint32_t)(wn * 64 + (lane & 7) + ((lane >> 4) & 1) * 8)
                         * (PSTR * 2) + ((lane >> 3) & 1) * 16;

    issue(0, 0);
    CP_COMMIT();

    const int NC = C_ / 64;   // 16
    for (int kc = 0; kc < NC; kc++) {
        CP_WAIT0();           // chunk kc resident (issued last iteration)
        __syncthreads();      // all warps past compute(kc-1); safe to overwrite
        if (kc + 1 < NC) {
            issue(kc + 1, (kc + 1) & 1);
            CP_COMMIT();      // flies during compute(kc)
        }

        const uint32_t sa   = base + (uint32_t)((kc & 1) * PSTAGE) * 2;
        const uint32_t sx_b = sa;
        const uint32_t sw_b = sa + (uint32_t)PAARR * 2;

#pragma unroll
        for (int u = 0; u < 4; u++) {
            uint32_t a0[4], a1[4];
            ldsm4(a0, sx_b + a_off + u * 32);
            ldsm4(a1, sx_b + a_off + (uint32_t)16 * (PSTR * 2) + u * 32);
#pragma unroll
            for (int jp = 0; jp < 4; jp++) {
                uint32_t bh[4];
                ldsm4(bh, sw_b + b_off + (uint32_t)jp * 16 * (PSTR * 2) + u * 32);
                mma16816(of[2 * jp],         a0, bh[0], bh[1]);
                mma16816(of[2 * jp + 1],     a0, bh[2], bh[3]);
                mma16816(of[8 + 2 * jp],     a1, bh[0], bh[1]);
                mma16816(of[8 + 2 * jp + 1], a1, bh[2], bh[3]);
            }
        }
    }

    // q scale folds softmax 1/sqrt(H) AND log2(e) (flash works in exp2 domain)
    const float scl = (sel == 0) ? (1.4426950408889634f * 0.08838834764831845f)
                                 : 1.0f;
    __half* op = (sel == 0) ? g_q16 : (sel == 1) ? g_k16 : g_v16;
#pragma unroll
    for (int j = 0; j < 16; j++) {
        const int mf = j >> 3;
        const int jp = (j >> 1) & 3;
        const int h  = j & 1;
#pragma unroll
        for (int i = 0; i < 2; i++) {
            const size_t row = (size_t)(m0 + wm * 32 + mf * 16 + (lane >> 2) + 8 * i);
            const int col = wn * 64 + jp * 16 + h * 8 + (lane & 3) * 2;
            *(uint32_t*)&op[row * H_ + col] =
                pack_h2(of[j][2 * i] * scl, of[j][2 * i + 1] * scl);
        }
    }
}

// ---- flash attention: producer-warp mbarrier pipeline, no steady-state sync --
// 9 warps: warps 0-7 consume (16 q-rows each), warp 8 produces KV via cp.async
// + mbarrier. 4-stage ring; consumers free-run and de-phase (lockstep killer).
#define FSTR   136
#define FQ     (128 * FSTR)
#define FKV    (64 * FSTR)
#define FSTAGE (2 * FKV)                      // K + V
#define F_SMEM ((FQ + 4 * FSTAGE) * 2)        // 174080 B

__global__ __launch_bounds__(288) void flash_kernel(float* __restrict__ out)
{
    extern __shared__ __half fs[];
    __shared__ __align__(8) uint64_t s_mbar[8];   // full[0..3], empty[0..3]
    __half* sq = fs;

    const int tid = threadIdx.x, lane = tid & 31, w = tid >> 5;   // w: 0..8
    const int b   = blockIdx.x;
    const int r0  = (gridDim.y - 1 - blockIdx.y) * 128;   // heavy rows first
    const uint32_t base   = smem_u32(fs);
    const uint32_t kvbase = base + (uint32_t)FQ * 2;
    const uint32_t mbar0  = smem_u32(&s_mbar[0]);
    auto mb_full  = [&](int s) { return mbar0 + (uint32_t)s * 8; };
    auto mb_empty = [&](int s) { return mbar0 + 32 + (uint32_t)s * 8; };

    const size_t bbase  = (size_t)b * T_ * H_;
    const int    ntiles = r0 / 64 + 2;

    if (tid == 0) {
#pragma unroll
        for (int s = 0; s < 4; s++) {
            MBAR_INIT(mb_full(s), 32);   // 32 producer-lane cp-arrivals
            MBAR_INIT(mb_empty(s), 8);   // 8 consumer-warp arrivals
        }
    }

    // Q tile load: consumer threads only (2048 uint4 over 256 threads)
    if (tid < 256) {
        const uint4* qp = (const uint4*)(g_q16 + bbase + (size_t)r0 * H_);
#pragma unroll
        for (int it = 0; it < 8; it++) {
            int i = tid + it * 256;
            int row = i >> 4, c8 = (i & 15) * 8;
            *(uint4*)&sq[row * FSTR + c8] = qp[i];
        }
    }
    __syncthreads();   // mbarriers initialized + Q resident

    if (w == 8) {
        // ---------------- producer warp ----------------
        int phase = 1;                    // fresh empty barriers: wait passes
        for (int t = 0; t < ntiles; t++) {
            const int s = t & 3;
            MBAR_WAIT(mb_empty(s), phase);
            const uint32_t sb = kvbase + (uint32_t)(s * FSTAGE) * 2;
            const __half* kp = g_k16 + bbase + (size_t)t * 64 * H_;
            const __half* vp = g_v16 + bbase + (size_t)t * 64 * H_;
#pragma unroll 8
            for (int j = 0; j < 32; j++) {
                int i   = lane + j * 32;        // 0..1023
                int row = i >> 4, c8 = (i & 15) * 8;
                uint32_t so = (uint32_t)(row * FSTR + c8) * 2;
                CP16(sb + so,           (const char*)(kp + row * H_ + c8));
                CP16(sb + FKV * 2 + so, (const char*)(vp + row * H_ + c8));
            }
            CP_MBAR_ARRIVE(mb_full(s));   // arrives when this lane's cps land
            if (s == 3) phase ^= 1;
        }
        return;
    }

    // ---------------- consumer warps (0..7) ----------------
    const int wr0 = w * 16;
    const uint32_t qa_off = (uint32_t)(wr0 + (lane & 15)) * (FSTR * 2) + (lane >> 4) * 16;
    const uint32_t kb_off = (uint32_t)((lane & 7) + ((lane >> 4) & 1) * 8) * (FSTR * 2)
                          + ((lane >> 3) & 1) * 16;
    const uint32_t vb_off = (uint32_t)((lane & 7) + ((lane >> 3) & 1) * 8) * (FSTR * 2)
                          + ((lane >> 4) & 1) * 16;

    uint32_t qf[8][4];
#pragma unroll
    for (int u = 0; u < 8; u++) ldsm4(qf[u], base + qa_off + u * 32);

    float of[16][4];
#pragma unroll
    for (int j = 0; j < 16; j++)
#pragma unroll
        for (int e = 0; e < 4; e++) of[j][e] = 0.f;
    float m_i[2] = {-1e30f, -1e30f}, l_i[2] = {0.f, 0.f};

    int phase = 0;
    for (int t = 0; t < ntiles; t++) {
        const int s0 = t * 64;
        const int s  = t & 3;
        MBAR_WAIT(mb_full(s), phase);

        const uint32_t sb   = kvbase + (uint32_t)(s * FSTAGE) * 2;
        const uint32_t sk_b = sb;
        const uint32_t sv_b = sb + FKV * 2;

        // ---- S = Q K^T  (logits already in log2 domain via q scale) ----
        float sf[8][4];
#pragma unroll
        for (int j = 0; j < 8; j++)
#pragma unroll
            for (int e = 0; e < 4; e++) sf[j][e] = 0.f;

#pragma unroll
        for (int u = 0; u < 8; u++) {
#pragma unroll
            for (int jp = 0; jp < 4; jp++) {
                uint32_t bh[4];
                ldsm4(bh, sk_b + kb_off + (uint32_t)jp * 16 * (FSTR * 2) + u * 32);
                mma16816(sf[2 * jp],     qf[u], bh[0], bh[1]);
                mma16816(sf[2 * jp + 1], qf[u], bh[2], bh[3]);
            }
        }

        // ---- causal mask ----
        const int rowg0 = r0 + wr0 + (lane >> 2);
        if (s0 + 63 > rowg0) {
#pragma unroll
            for (int j = 0; j < 8; j++) {
                const int colg = s0 + 8 * j + (lane & 3) * 2;
#pragma unroll
                for (int i = 0; i < 2; i++) {
                    const int rg = rowg0 + 8 * i;
                    if (colg     > rg) sf[j][2 * i]     = -1e30f;
                    if (colg + 1 > rg) sf[j][2 * i + 1] = -1e30f;
                }
            }
        }

        // ---- online softmax (exp2 domain, 2-wide f16 EX2 -> packed P) ----
        uint32_t pf[8][2];
#pragma unroll
        for (int i = 0; i < 2; i++) {
            float mx = sf[0][2 * i];
#pragma unroll
            for (int j = 0; j < 8; j++) {
                mx = fmaxf(mx, sf[j][2 * i]);
                mx = fmaxf(mx, sf[j][2 * i + 1]);
            }
            mx = fmaxf(mx, __shfl_xor_sync(0xffffffffu, mx, 1));
            mx = fmaxf(mx, __shfl_xor_sync(0xffffffffu, mx, 2));
            const float mn  = fmaxf(m_i[i], mx);
            const float fac = exp2f(m_i[i] - mn);
            m_i[i] = mn;
            float rs = 0.f;
#pragma unroll
            for (int j = 0; j < 8; j++) {
                const uint32_t p2 = exp2_h2(sf[j][2 * i] - mn, sf[j][2 * i + 1] - mn);
                pf[j][i] = p2;
                const float2 pv = __half22float2(*reinterpret_cast<const __half2*>(&p2));
                rs += pv.x + pv.y;
            }
            rs += __shfl_xor_sync(0xffffffffu, rs, 1);
            rs += __shfl_xor_sync(0xffffffffu, rs, 2);
            l_i[i] = l_i[i] * fac + rs;
#pragma unroll
            for (int j = 0; j < 16; j++) {
                of[j][2 * i] *= fac; of[j][2 * i + 1] *= fac;
            }
        }

        // ---- O += P V ----
#pragma unroll
        for (int u = 0; u < 4; u++) {
            uint32_t ph[4];
            ph[0] = pf[2 * u][0];
            ph[1] = pf[2 * u][1];
            ph[2] = pf[2 * u + 1][0];
            ph[3] = pf[2 * u + 1][1];
#pragma unroll
            for (int jp = 0; jp < 8; jp++) {
                uint32_t vh[4];
                ldsm4t(vh, sv_b + vb_off + (uint32_t)u * 16 * (FSTR * 2) + jp * 32);
                mma16816(of[2 * jp],     ph, vh[0], vh[1]);
                mma16816(of[2 * jp + 1], ph, vh[2], vh[3]);
            }
        }

        // done reading stage s (K in S-phase, V just now): free it
        if (lane == 0) MBAR_ARRIVE(mb_empty(s));
        if (s == 3) phase ^= 1;
    }

    // ---- write O ----
    const float inv0 = 1.0f / l_i[0], inv1 = 1.0f / l_i[1];
#pragma unroll
    for (int j = 0; j < 16; j++)
#pragma unroll
        for (int i = 0; i < 2; i++) {
            const size_t row = (size_t)b * T_ + r0 + wr0 + (lane >> 2) + 8 * i;
            const int col = 8 * j + (lane & 3) * 2;
            const float inv = i ? inv1 : inv0;
            float2 v = make_float2(of[j][2 * i] * inv, of[j][2 * i + 1] * inv);
            *(float2*)&out[row * H_ + col] = v;
        }
}

// ---------------------------------------------------------------------------
extern "C" void kernel_launch(void* const* d_in, const int* in_sizes, int n_in,
                              void* d_out, int out_size)
{
    const float* x  = (const float*)d_in[0];
    const float* Wk = (const float*)d_in[1];
    const float* Wq = (const float*)d_in[2];
    const float* Wv = (const float*)d_in[3];
    float* out = (float*)d_out;

    cudaFuncSetAttribute(qkv_mma_kernel,
                         cudaFuncAttributeMaxDynamicSharedMemorySize, P_SMEM);
    cudaFuncSetAttribute(flash_kernel,
                         cudaFuncAttributeMaxDynamicSharedMemorySize, F_SMEM);

    convert_x_kernel<<<(M_ * (size_t)C_ / 4) / 256, 256>>>(x);
    convert_w_kernel<<<dim3((H_ * C_ / 4) / 256, 3, 1), 256>>>(Wk, Wq, Wv);
    qkv_mma_kernel<<<dim3(3, M_ / 64, 1), 128, P_SMEM>>>();
    flash_kernel<<<dim3(B_, T_ / 128, 1), 288, F_SMEM>>>(out);
}